// round 15
// baseline (speedup 1.0000x reference)
#include <cuda_runtime.h>
#include <cuda_fp16.h>
#include <math.h>
#include <cstdint>

#define B_   8
#define T_   1024
#define E_   1024
#define H_   16
#define D_   64
#define BH_  (B_*H_)   /* 128 */
#define M_   (B_*T_)   /* 8192 */

// ---------------- device scratch (no allocations allowed) ----------------
__device__ __align__(256) __half g_X3[(size_t)3 * M_ * E_];  // q,k,v acts; slot0 reused for C
__device__ __align__(256) __half g_W3[(size_t)3 * E_ * E_];  // wq,wk,wv
__device__ __align__(256) __half g_Wo[(size_t)E_ * E_];      // wo
__device__ __align__(256) __half g_Qh[(size_t)BH_ * T_ * D_];   // post-xpos, [bh,t,d]
__device__ __align__(256) __half g_Kh[(size_t)BH_ * T_ * D_];
__device__ __align__(256) __half g_Vt[(size_t)BH_ * D_ * T_];   // [bh,d,s]

// ================= PTX helpers =================
__device__ __forceinline__ uint32_t smem_u32(const void* p) {
    uint32_t a;
    asm("{ .reg .u64 t; cvta.to.shared.u64 t, %1; cvt.u32.u64 %0, t; }" : "=r"(a) : "l"(p));
    return a;
}
__device__ __forceinline__ void ldsm_x4(uint32_t& r0, uint32_t& r1, uint32_t& r2, uint32_t& r3,
                                        uint32_t addr) {
    asm volatile("ldmatrix.sync.aligned.m8n8.x4.shared.b16 {%0,%1,%2,%3}, [%4];"
                 : "=r"(r0), "=r"(r1), "=r"(r2), "=r"(r3) : "r"(addr));
}
__device__ __forceinline__ void mma_f16(float* d, const uint32_t* a, const uint32_t* b) {
    asm volatile(
        "mma.sync.aligned.m16n8k16.row.col.f32.f16.f16.f32 "
        "{%0,%1,%2,%3}, {%4,%5,%6,%7}, {%8,%9}, {%0,%1,%2,%3};"
        : "+f"(d[0]), "+f"(d[1]), "+f"(d[2]), "+f"(d[3])
        : "r"(a[0]), "r"(a[1]), "r"(a[2]), "r"(a[3]), "r"(b[0]), "r"(b[1]));
}
#define CP_ASYNC16(dst, src) \
    asm volatile("cp.async.cg.shared.global [%0], [%1], 16;" :: "r"(dst), "l"(src))
#define CP_COMMIT() asm volatile("cp.async.commit_group;" ::: "memory")
#define CP_WAIT0()  asm volatile("cp.async.wait_group 0;" ::: "memory")
#define CP_WAIT1()  asm volatile("cp.async.wait_group 1;" ::: "memory")

__device__ __forceinline__ uint32_t pack_h2(float x, float y) {
    __half2 t = __floats2half2_rn(x, y);
    return *reinterpret_cast<uint32_t*>(&t);
}

// ================= fp32 -> fp16 convert, 16 elts/thread, all 7 tensors =================
__global__ __launch_bounds__(256) void conv_all(
    const float* __restrict__ q, const float* __restrict__ k, const float* __restrict__ v,
    const float* __restrict__ wq, const float* __restrict__ wk, const float* __restrict__ wv,
    const float* __restrict__ wo)
{
    const int z = blockIdx.z;
    const int actn16 = (M_ * E_) / 16;
    const int wn16   = (E_ * E_) / 16;
    const int n16 = (z < 3) ? actn16 : wn16;
    int idx = blockIdx.x * blockDim.x + threadIdx.x;
    if (idx >= n16) return;

    const float* x;
    __half* y;
    switch (z) {
        case 0: x = q;  y = g_X3;                       break;
        case 1: x = k;  y = g_X3 + (size_t)M_ * E_;     break;
        case 2: x = v;  y = g_X3 + (size_t)2 * M_ * E_; break;
        case 3: x = wq; y = g_W3;                       break;
        case 4: x = wk; y = g_W3 + (size_t)E_ * E_;     break;
        case 5: x = wv; y = g_W3 + (size_t)2 * E_ * E_; break;
        default: x = wo; y = g_Wo;                      break;
    }
    const float* xp = x + (size_t)idx * 16;
    // two independent 8-element groups (4 loads in flight)
    float4 a0 = *reinterpret_cast<const float4*>(xp);
    float4 a1 = *reinterpret_cast<const float4*>(xp + 4);
    float4 b0 = *reinterpret_cast<const float4*>(xp + 8);
    float4 b1 = *reinterpret_cast<const float4*>(xp + 12);
    __half ha[8], hb[8];
    ha[0] = __float2half_rn(a0.x); ha[1] = __float2half_rn(a0.y);
    ha[2] = __float2half_rn(a0.z); ha[3] = __float2half_rn(a0.w);
    ha[4] = __float2half_rn(a1.x); ha[5] = __float2half_rn(a1.y);
    ha[6] = __float2half_rn(a1.z); ha[7] = __float2half_rn(a1.w);
    hb[0] = __float2half_rn(b0.x); hb[1] = __float2half_rn(b0.y);
    hb[2] = __float2half_rn(b0.z); hb[3] = __float2half_rn(b0.w);
    hb[4] = __float2half_rn(b1.x); hb[5] = __float2half_rn(b1.y);
    hb[6] = __float2half_rn(b1.z); hb[7] = __float2half_rn(b1.w);
    *reinterpret_cast<uint4*>(y + (size_t)idx * 16)     = *reinterpret_cast<uint4*>(ha);
    *reinterpret_cast<uint4*>(y + (size_t)idx * 16 + 8) = *reinterpret_cast<uint4*>(hb);
}

// ================= 2-stage x 2-chunk, register-pipelined fp16 GEMM =================
// 256 threads = 8 warps; CTA tile 128x128; warp tile 64x32; BK=32 per sub-chunk,
// 2 sub-chunks per stage (BK=64 per stage) -> 16 sync rounds instead of 32.
#define BKC      32
#define ROWB     80                       /* 64B data + 16B pad */
#define SUBTILE_B (128 * ROWB)            /* 10240 (A or B sub-tile) */
#define SUBPAIR_B (2 * SUBTILE_B)         /* 20480 (A+B for one sub-chunk) */
#define STAGE_B   (2 * SUBPAIR_B)         /* 40960 (2 sub-chunks) */
#define GEMM_SMEM (2 * STAGE_B)           /* 81920 */
#define N_PAIRS  16

__device__ __forceinline__ void gemm_mainloop(
    uint32_t sbase, const __half* __restrict__ X, const __half* __restrict__ W,
    int m0, int n0, float acc[4][4][4])
{
    const int tid  = threadIdx.x;
    const int wid  = tid >> 5;
    const int lane = tid & 31;
    const int m_w = (wid & 1) * 64;
    const int n_w = (wid >> 1) * 32;

    uint32_t l_soff[2];
    int l_row[2], l_col[2];
    #pragma unroll
    for (int i = 0; i < 2; i++) {
        int idx = tid + i * 256;
        l_row[i] = idx >> 2; l_col[i] = (idx & 3) * 8;
        l_soff[i] = (uint32_t)l_row[i] * ROWB + (idx & 3) * 16;
    }

    #pragma unroll
    for (int i = 0; i < 4; i++)
        #pragma unroll
        for (int j = 0; j < 4; j++)
            #pragma unroll
            for (int q = 0; q < 4; q++) acc[i][j][q] = 0.f;

    const uint32_t a_base = (uint32_t)(m_w + (lane & 15)) * ROWB + (lane >> 4) * 16;
    const int bg = lane >> 3;
    const uint32_t b_rowoff = (uint32_t)(n_w + ((bg >> 1) * 8) + (lane & 7)) * ROWB;
    const uint32_t b_col = (uint32_t)(bg & 1) * 16;

    // issue both sub-chunks of pair p into stage s
    auto issue = [&](int p, int s) {
        #pragma unroll
        for (int sub = 0; sub < 2; sub++) {
            const int c = 2 * p + sub;
            const __half* sa = X + (size_t)m0 * E_ + c * BKC;
            const __half* sw = W + (size_t)n0 * E_ + c * BKC;
            const uint32_t ab = sbase + (uint32_t)s * STAGE_B + (uint32_t)sub * SUBPAIR_B;
            const uint32_t bb = ab + SUBTILE_B;
            #pragma unroll
            for (int i = 0; i < 2; i++) {
                CP_ASYNC16(ab + l_soff[i], sa + (size_t)l_row[i] * E_ + l_col[i]);
                CP_ASYNC16(bb + l_soff[i], sw + (size_t)l_row[i] * E_ + l_col[i]);
            }
        }
    };

    // ks in 0..3: sub = ks>>1, inner k-step = ks&1
    auto load_frags = [&](uint32_t stage_base, int ks, uint32_t af[4][4], uint32_t bf[4][2]) {
        const uint32_t base = stage_base + (uint32_t)(ks >> 1) * SUBPAIR_B;
        const int inner = ks & 1;
        const uint32_t at = base;
        const uint32_t bt = base + SUBTILE_B;
        #pragma unroll
        for (int mf = 0; mf < 4; mf++)
            ldsm_x4(af[mf][0], af[mf][1], af[mf][2], af[mf][3],
                    at + a_base + (uint32_t)mf * 16 * ROWB + inner * 32);
        #pragma unroll
        for (int nf2 = 0; nf2 < 2; nf2++) {
            uint32_t r0, r1, r2, r3;
            ldsm_x4(r0, r1, r2, r3,
                    bt + b_rowoff + (uint32_t)nf2 * 16 * ROWB + b_col + inner * 32);
            bf[nf2 * 2 + 0][0] = r0; bf[nf2 * 2 + 0][1] = r1;
            bf[nf2 * 2 + 1][0] = r2; bf[nf2 * 2 + 1][1] = r3;
        }
    };

    auto mma_all = [&](uint32_t af[4][4], uint32_t bf[4][2]) {
        #pragma unroll
        for (int mf = 0; mf < 4; mf++)
            #pragma unroll
            for (int nf = 0; nf < 4; nf++)
                mma_f16(acc[mf][nf], af[mf], bf[nf]);
    };

    // prologue: pairs 0,1 in flight
    issue(0, 0); CP_COMMIT();
    issue(1, 1); CP_COMMIT();
    CP_WAIT1();            // pair 0 resident (per-thread)
    __syncthreads();       // cross-thread visibility
    uint32_t afA[4][4], bfA[4][2];
    uint32_t afB[4][4], bfB[4][2];
    load_frags(sbase, 0, afA, bfA);

    for (int it = 0; it < N_PAIRS; ++it) {
        const int buf = it & 1;
        const uint32_t st = sbase + (uint32_t)buf * STAGE_B;

        load_frags(st, 1, afB, bfB);
        mma_all(afA, bfA);             // ks0
        load_frags(st, 2, afA, bfA);
        mma_all(afB, bfB);             // ks1
        load_frags(st, 3, afB, bfB);
        mma_all(afA, bfA);             // ks2

        CP_WAIT0();                    // pair it+1 resident (per-thread)
        __syncthreads();               // visibility + all warps done reading stage buf
        if (it + 2 < N_PAIRS) issue(it + 2, buf);
        CP_COMMIT();

        if (it + 1 < N_PAIRS)
            load_frags(sbase + (uint32_t)((it + 1) & 1) * STAGE_B, 0, afA, bfA);
        mma_all(afB, bfB);             // ks3
    }
}

// ---------------- merged QKV projection with fused xpos / transpose epilogues ----------------
__global__ __launch_bounds__(256, 2) void gemm_qkv(
    const float* __restrict__ bq, const float* __restrict__ bk, const float* __restrict__ bv)
{
    extern __shared__ char smem[];
    const uint32_t sbase = smem_u32(smem);
    const int z = blockIdx.z;
    const int m0 = blockIdx.y * 128;
    const int n0 = blockIdx.x * 128;
    const float* bias = (z == 0) ? bq : (z == 1) ? bk : bv;

    float acc[4][4][4];
    gemm_mainloop(sbase, g_X3 + (size_t)z * M_ * E_, g_W3 + (size_t)z * E_ * E_,
                  m0, n0, acc);

    const int tid  = threadIdx.x;
    const int wid  = tid >> 5;
    const int lane = tid & 31;
    const int m_w = (wid & 1) * 64;
    const int n_w = (wid >> 1) * 32;

    if (z < 2) {
        __half* O = (z == 0) ? g_Qh : g_Kh;
        const float alpha = (z == 0) ? 0.125f : 1.f;
        const float sgn = (z == 0) ? 1.f : -1.f;

        float lsj[4], ivf[4];
        #pragma unroll
        for (int nf = 0; nf < 4; nf++) {
            int n = n0 + n_w + nf * 8 + (lane & 3) * 2;
            int j = (n & 63) >> 1;
            float sj = (2.f * j + 25.6f) / 89.6f;
            lsj[nf] = log2f(sj) * (sgn / 1024.f);
            ivf[nf] = exp2f(-(float)j * (13.287712379549449f / 32.f));
        }

        #pragma unroll
        for (int mf = 0; mf < 4; mf++) {
            #pragma unroll
            for (int half = 0; half < 2; half++) {
                const int m = m0 + m_w + mf * 16 + (lane >> 2) + half * 8;
                const int bb = m >> 10;
                const int t  = m & 1023;
                const float pos = (float)(t - 512);
                #pragma unroll
                for (int nf = 0; nf < 4; nf++) {
                    const int n = n0 + n_w + nf * 8 + (lane & 3) * 2;
                    const int h = n >> 6, d = n & 63;
                    float y1 = (acc[mf][nf][half * 2 + 0] + __ldg(bias + n)) * alpha;
                    float y2 = (acc[mf][nf][half * 2 + 1] + __ldg(bias + n + 1)) * alpha;
                    float sc = exp2f(lsj[nf] * pos);
                    float sn, cs;
                    sincosf((float)t * ivf[nf], &sn, &cs);
                    cs *= sc; sn *= sc;
                    float o1 = y1 * cs - y2 * sn;
                    float o2 = y2 * cs + y1 * sn;
                    size_t ob = (((size_t)(bb * H_ + h)) * T_ + t) * D_ + d;
                    *reinterpret_cast<uint32_t*>(O + ob) = pack_h2(o1, o2);
                }
            }
        }
    } else {
        float* tr = reinterpret_cast<float*>(smem);   // [64][132] fp32 = 33792 B
        __syncthreads();
        #pragma unroll
        for (int half_n = 0; half_n < 2; half_n++) {
            if (((wid >> 1) >> 1) == half_n) {
                #pragma unroll
                for (int mf = 0; mf < 4; mf++)
                    #pragma unroll
                    for (int half = 0; half < 2; half++) {
                        const int m_local = m_w + mf * 16 + (lane >> 2) + half * 8;
                        #pragma unroll
                        for (int nf = 0; nf < 4; nf++) {
                            const int dd = ((wid >> 1) & 1) * 32 + nf * 8 + (lane & 3) * 2;
                            const int n = n0 + half_n * 64 + dd;
                            tr[dd * 132 + m_local] =
                                acc[mf][nf][half * 2 + 0] + __ldg(bias + n);
                            tr[(dd + 1) * 132 + m_local] =
                                acc[mf][nf][half * 2 + 1] + __ldg(bias + n + 1);
                        }
                    }
            }
            __syncthreads();
            {
                const int d = tid >> 2;
                const int tpart = (tid & 3) * 32;
                const int h = (n0 >> 6) + half_n;
                const int bh = (m0 >> 10) * H_ + h;
                const size_t ob = ((size_t)bh * D_ + d) * T_ + (m0 & 1023) + tpart;
                const float* row = tr + d * 132 + tpart;
                #pragma unroll
                for (int k = 0; k < 32; k += 2) {
                    *reinterpret_cast<uint32_t*>(g_Vt + ob + k) =
                        pack_h2(row[k], row[k + 1]);
                }
            }
            __syncthreads();
        }
    }
}

// ---------------- output projection ----------------
__global__ __launch_bounds__(256, 2) void gemm_out(
    const float* __restrict__ bias, float* __restrict__ out)
{
    extern __shared__ char smem[];
    const uint32_t sbase = smem_u32(smem);
    const int m0 = blockIdx.y * 128;
    const int n0 = blockIdx.x * 128;

    float acc[4][4][4];
    gemm_mainloop(sbase, g_X3, g_Wo, m0, n0, acc);

    const int tid  = threadIdx.x;
    const int wid  = tid >> 5;
    const int lane = tid & 31;
    const int m_w = (wid & 1) * 64;
    const int n_w = (wid >> 1) * 32;

    #pragma unroll
    for (int mf = 0; mf < 4; mf++) {
        #pragma unroll
        for (int half = 0; half < 2; half++) {
            const int m = m0 + m_w + mf * 16 + (lane >> 2) + half * 8;
            #pragma unroll
            for (int nf = 0; nf < 4; nf++) {
                const int n = n0 + n_w + nf * 8 + (lane & 3) * 2;
                float2 v;
                v.x = acc[mf][nf][half * 2 + 0] + __ldg(bias + n);
                v.y = acc[mf][nf][half * 2 + 1] + __ldg(bias + n + 1);
                *reinterpret_cast<float2*>(out + (size_t)m * E_ + n) = v;
            }
        }
    }
}

// ================= Flash attention, fp16, fixed-shift softmax (R14 proven) =================
#define ASM_ST0  8192
#define ASM_STS  16384
#define ATTN_SMEM 40960

__global__ __launch_bounds__(128) void attn_mma()
{
    extern __shared__ char smem[];
    const uint32_t sb = smem_u32(smem);
    const int tid  = threadIdx.x;
    const int wid  = tid >> 5;
    const int lane = tid & 31;
    const int bh = blockIdx.x;
    const int qt = blockIdx.y;

    auto issue_kv = [&](int st, int s) {
        const int s0 = st * 64;
        const uint32_t base = sb + ASM_ST0 + (uint32_t)s * ASM_STS;
        const __half* kh = g_Kh + ((size_t)bh * T_ + s0) * D_;
        const __half* vh = g_Vt + (size_t)bh * D_ * T_ + s0;
        #pragma unroll
        for (int i = 0; i < 4; i++) {
            int idx = tid + i * 128;
            int row = idx >> 3, seg = idx & 7;
            uint32_t off = (uint32_t)row * 128 + ((seg ^ (row & 7)) * 16);
            CP_ASYNC16(base + off,        kh + (size_t)row * D_ + seg * 8);
            CP_ASYNC16(base + 8192 + off, vh + (size_t)row * T_ + seg * 8);
        }
    };

    {
        const __half* qh = g_Qh + ((size_t)bh * T_ + qt * 64) * D_;
        #pragma unroll
        for (int i = 0; i < 4; i++) {
            int idx = tid + i * 128;
            int row = idx >> 3, seg = idx & 7;
            uint32_t off = (uint32_t)row * 128 + ((seg ^ (row & 7)) * 16);
            CP_ASYNC16(sb + off, qh + (size_t)row * D_ + seg * 8);
        }
        issue_kv(0, 0);
        CP_COMMIT(); CP_WAIT0();
        __syncthreads();
    }

    uint32_t qf[4][4];
    {
        const int row = wid * 16 + (lane & 15);
        const uint32_t rb = (uint32_t)row * 128;
        #pragma unroll
        for (int ks = 0; ks < 4; ks++) {
            int seg = ks * 2 + (lane >> 4);
            uint32_t off = rb + ((seg ^ (row & 7)) * 16);
            ldsm_x4(qf[ks][0], qf[ks][1], qf[ks][2], qf[ks][3], sb + off);
        }
    }

    float l0 = 0.f, l1 = 0.f;
    float o[8][4];
    #pragma unroll
    for (int nf = 0; nf < 8; nf++)
        #pragma unroll
        for (int q = 0; q < 4; q++) o[nf][q] = 0.f;

    const int bg = lane >> 3;
    const int brow_lo = ((bg >> 1) * 8) + (lane & 7);
    const int bseg0 = bg & 1;

    for (int st = 0; st < 16; st++) {
        const int buf = st & 1;
        if (st + 1 < 16) issue_kv(st + 1, buf ^ 1);
        CP_COMMIT();

        const uint32_t kbase = sb + ASM_ST0 + (uint32_t)buf * ASM_STS;
        const uint32_t vbase = kbase + 8192;

        float sacc[8][4];
        #pragma unroll
        for (int nf = 0; nf < 8; nf++)
            #pragma unroll
            for (int q = 0; q < 4; q++) sacc[nf][q] = 0.f;

        #pragma unroll
        for (int ks = 0; ks < 4; ks++) {
            uint32_t bf[8][2];
            #pragma unroll
            for (int nf2 = 0; nf2 < 4; nf2++) {
                int row = nf2 * 16 + brow_lo;
                int seg = (ks * 2 + bseg0) ^ (row & 7);
                uint32_t r0, r1, r2, r3;
                ldsm_x4(r0, r1, r2, r3, kbase + (uint32_t)row * 128 + seg * 16);
                bf[nf2 * 2 + 0][0] = r0; bf[nf2 * 2 + 0][1] = r1;
                bf[nf2 * 2 + 1][0] = r2; bf[nf2 * 2 + 1][1] = r3;
            }
            #pragma unroll
            for (int nf = 0; nf < 8; nf++)
                mma_f16(sacc[nf], qf[ks], bf[nf]);
        }

        #pragma unroll
        for (int nf = 0; nf < 8; nf++) {
            float e0 = __expf(sacc[nf][0]);
            float e1 = __expf(sacc[nf][1]);
            float e2 = __expf(sacc[nf][2]);
            float e3 = __expf(sacc[nf][3]);
            l0 += e0 + e1; l1 += e2 + e3;
            sacc[nf][0] = e0; sacc[nf][1] = e1;
            sacc[nf][2] = e2; sacc[nf][3] = e3;
        }

        uint32_t pf[4][4];
        #pragma unroll
        for (int ks = 0; ks < 4; ks++) {
            pf[ks][0] = pack_h2(sacc[2 * ks][0],     sacc[2 * ks][1]);
            pf[ks][1] = pack_h2(sacc[2 * ks][2],     sacc[2 * ks][3]);
            pf[ks][2] = pack_h2(sacc[2 * ks + 1][0], sacc[2 * ks + 1][1]);
            pf[ks][3] = pack_h2(sacc[2 * ks + 1][2], sacc[2 * ks + 1][3]);
        }

        #pragma unroll
        for (int ks = 0; ks < 4; ks++) {
            uint32_t bf[8][2];
            #pragma unroll
            for (int nf2 = 0; nf2 < 4; nf2++) {
                int row = nf2 * 16 + brow_lo;
                int seg = (ks * 2 + bseg0) ^ (row & 7);
                uint32_t r0, r1, r2, r3;
                ldsm_x4(r0, r1, r2, r3, vbase + (uint32_t)row * 128 + seg * 16);
                bf[nf2 * 2 + 0][0] = r0; bf[nf2 * 2 + 0][1] = r1;
                bf[nf2 * 2 + 1][0] = r2; bf[nf2 * 2 + 1][1] = r3;
            }
            #pragma unroll
            for (int nf = 0; nf < 8; nf++)
                mma_f16(o[nf], pf[ks], bf[nf]);
        }

        CP_WAIT0();
        __syncthreads();
    }

    l0 += __shfl_xor_sync(0xffffffffu, l0, 1);
    l0 += __shfl_xor_sync(0xffffffffu, l0, 2);
    l1 += __shfl_xor_sync(0xffffffffu, l1, 1);
    l1 += __shfl_xor_sync(0xffffffffu, l1, 2);
    const float inv0 = 1.f / l0;
    const float inv1 = 1.f / l1;

    const int t0 = qt * 64 + wid * 16 + (lane >> 2);
    const int b = bh >> 4, h = bh & 15;
    const size_t c0i = ((size_t)(b * T_ + t0)) * E_ + h * D_ + (lane & 3) * 2;
    const size_t c1i = c0i + (size_t)8 * E_;
    #pragma unroll
    for (int nf = 0; nf < 8; nf++) {
        *reinterpret_cast<uint32_t*>(g_X3 + c0i + nf * 8) =
            pack_h2(o[nf][0] * inv0, o[nf][1] * inv0);
        *reinterpret_cast<uint32_t*>(g_X3 + c1i + nf * 8) =
            pack_h2(o[nf][2] * inv1, o[nf][3] * inv1);
    }
}

// ---------------- launch ----------------
extern "C" void kernel_launch(void* const* d_in, const int* in_sizes, int n_in,
                              void* d_out, int out_size)
{
    const float* query = (const float*)d_in[0];
    const float* key   = (const float*)d_in[1];
    const float* value = (const float*)d_in[2];
    const float* wq    = (const float*)d_in[3];
    const float* bq    = (const float*)d_in[4];
    const float* wk    = (const float*)d_in[5];
    const float* bk    = (const float*)d_in[6];
    const float* wv    = (const float*)d_in[7];
    const float* bv    = (const float*)d_in[8];
    const float* wo    = (const float*)d_in[9];
    const float* bo    = (const float*)d_in[10];
    float* out = (float*)d_out;

    static bool attr_done = false;
    if (!attr_done) {
        cudaFuncSetAttribute(gemm_qkv, cudaFuncAttributeMaxDynamicSharedMemorySize, GEMM_SMEM);
        cudaFuncSetAttribute(gemm_out, cudaFuncAttributeMaxDynamicSharedMemorySize, GEMM_SMEM);
        cudaFuncSetAttribute(attn_mma, cudaFuncAttributeMaxDynamicSharedMemorySize, ATTN_SMEM);
        attr_done = true;
    }

    const int actn16 = (M_ * E_) / 16;   // 524,288

    conv_all<<<dim3(actn16 / 256, 1, 7), 256>>>(query, key, value, wq, wk, wv, wo);

    gemm_qkv<<<dim3(E_ / 128, M_ / 128, 3), 256, GEMM_SMEM>>>(bq, bk, bv);

    attn_mma<<<dim3(BH_, T_ / 64), 128, ATTN_SMEM>>>();   // writes C fp16 into X3 slot 0

    gemm_out<<<dim3(E_ / 128, M_ / 128), 256, GEMM_SMEM>>>(bo, out);
}

// round 16
// speedup vs baseline: 1.0492x; 1.0492x over previous
#include <cuda_runtime.h>
#include <cuda_fp16.h>
#include <math.h>
#include <cstdint>

#define B_   8
#define T_   1024
#define E_   1024
#define H_   16
#define D_   64
#define BH_  (B_*H_)   /* 128 */
#define M_   (B_*T_)   /* 8192 */

// ---------------- device scratch (no allocations allowed) ----------------
__device__ __align__(256) __half g_X3[(size_t)3 * M_ * E_];  // q,k,v acts; slot0 reused for C
__device__ __align__(256) __half g_W3[(size_t)3 * E_ * E_];  // wq,wk,wv
__device__ __align__(256) __half g_Wo[(size_t)E_ * E_];      // wo
__device__ __align__(256) __half g_Qh[(size_t)BH_ * T_ * D_];   // post-xpos, [bh,t,d]
__device__ __align__(256) __half g_Kh[(size_t)BH_ * T_ * D_];
__device__ __align__(256) __half g_Vt[(size_t)BH_ * D_ * T_];   // [bh,d,s]

// ================= PTX helpers =================
__device__ __forceinline__ uint32_t smem_u32(const void* p) {
    uint32_t a;
    asm("{ .reg .u64 t; cvta.to.shared.u64 t, %1; cvt.u32.u64 %0, t; }" : "=r"(a) : "l"(p));
    return a;
}
__device__ __forceinline__ void ldsm_x4(uint32_t& r0, uint32_t& r1, uint32_t& r2, uint32_t& r3,
                                        uint32_t addr) {
    asm volatile("ldmatrix.sync.aligned.m8n8.x4.shared.b16 {%0,%1,%2,%3}, [%4];"
                 : "=r"(r0), "=r"(r1), "=r"(r2), "=r"(r3) : "r"(addr));
}
__device__ __forceinline__ void mma_f16(float* d, const uint32_t* a, const uint32_t* b) {
    asm volatile(
        "mma.sync.aligned.m16n8k16.row.col.f32.f16.f16.f32 "
        "{%0,%1,%2,%3}, {%4,%5,%6,%7}, {%8,%9}, {%0,%1,%2,%3};"
        : "+f"(d[0]), "+f"(d[1]), "+f"(d[2]), "+f"(d[3])
        : "r"(a[0]), "r"(a[1]), "r"(a[2]), "r"(a[3]), "r"(b[0]), "r"(b[1]));
}
#define CP_ASYNC16(dst, src) \
    asm volatile("cp.async.cg.shared.global [%0], [%1], 16;" :: "r"(dst), "l"(src))
#define CP_COMMIT() asm volatile("cp.async.commit_group;" ::: "memory")
#define CP_WAIT0()  asm volatile("cp.async.wait_group 0;" ::: "memory")
#define CP_WAIT1()  asm volatile("cp.async.wait_group 1;" ::: "memory")
#define CP_WAIT2()  asm volatile("cp.async.wait_group 2;" ::: "memory")

__device__ __forceinline__ uint32_t pack_h2(float x, float y) {
    __half2 t = __floats2half2_rn(x, y);
    return *reinterpret_cast<uint32_t*>(&t);
}

// ================= fp32 -> fp16 convert, 16 elts/thread, all 7 tensors =================
__global__ __launch_bounds__(256) void conv_all(
    const float* __restrict__ q, const float* __restrict__ k, const float* __restrict__ v,
    const float* __restrict__ wq, const float* __restrict__ wk, const float* __restrict__ wv,
    const float* __restrict__ wo)
{
    const int z = blockIdx.z;
    const int actn16 = (M_ * E_) / 16;
    const int wn16   = (E_ * E_) / 16;
    const int n16 = (z < 3) ? actn16 : wn16;
    int idx = blockIdx.x * blockDim.x + threadIdx.x;
    if (idx >= n16) return;

    const float* x;
    __half* y;
    switch (z) {
        case 0: x = q;  y = g_X3;                       break;
        case 1: x = k;  y = g_X3 + (size_t)M_ * E_;     break;
        case 2: x = v;  y = g_X3 + (size_t)2 * M_ * E_; break;
        case 3: x = wq; y = g_W3;                       break;
        case 4: x = wk; y = g_W3 + (size_t)E_ * E_;     break;
        case 5: x = wv; y = g_W3 + (size_t)2 * E_ * E_; break;
        default: x = wo; y = g_Wo;                      break;
    }
    const float* xp = x + (size_t)idx * 16;
    float4 a0 = *reinterpret_cast<const float4*>(xp);
    float4 a1 = *reinterpret_cast<const float4*>(xp + 4);
    float4 b0 = *reinterpret_cast<const float4*>(xp + 8);
    float4 b1 = *reinterpret_cast<const float4*>(xp + 12);
    __half ha[8], hb[8];
    ha[0] = __float2half_rn(a0.x); ha[1] = __float2half_rn(a0.y);
    ha[2] = __float2half_rn(a0.z); ha[3] = __float2half_rn(a0.w);
    ha[4] = __float2half_rn(a1.x); ha[5] = __float2half_rn(a1.y);
    ha[6] = __float2half_rn(a1.z); ha[7] = __float2half_rn(a1.w);
    hb[0] = __float2half_rn(b0.x); hb[1] = __float2half_rn(b0.y);
    hb[2] = __float2half_rn(b0.z); hb[3] = __float2half_rn(b0.w);
    hb[4] = __float2half_rn(b1.x); hb[5] = __float2half_rn(b1.y);
    hb[6] = __float2half_rn(b1.z); hb[7] = __float2half_rn(b1.w);
    *reinterpret_cast<uint4*>(y + (size_t)idx * 16)     = *reinterpret_cast<uint4*>(ha);
    *reinterpret_cast<uint4*>(y + (size_t)idx * 16 + 8) = *reinterpret_cast<uint4*>(hb);
}

// ================= 3-stage, register-pipelined fp16 GEMM mainloop (R14 proven) =================
// 256 threads = 8 warps; CTA tile 128x128; warp tile 64x32; BK=32; K=1024.
#define BKC      32
#define ROWB     80                     /* 64B data + 16B pad */
#define TILE_B   (128 * ROWB)           /* 10240 */
#define STAGE_B  (2 * TILE_B)           /* 20480 */
#define GEMM_SMEM (3 * STAGE_B)         /* 61440 */
#define N_CHUNKS 32

__device__ __forceinline__ void gemm_mainloop(
    uint32_t sbase, const __half* __restrict__ X, const __half* __restrict__ W,
    int m0, int n0, float acc[4][4][4])
{
    const int tid  = threadIdx.x;
    const int wid  = tid >> 5;
    const int lane = tid & 31;
    const int m_w = (wid & 1) * 64;
    const int n_w = (wid >> 1) * 32;

    uint32_t l_soff[2];
    int l_row[2], l_col[2];
    #pragma unroll
    for (int i = 0; i < 2; i++) {
        int idx = tid + i * 256;
        l_row[i] = idx >> 2; l_col[i] = (idx & 3) * 8;
        l_soff[i] = (uint32_t)l_row[i] * ROWB + (idx & 3) * 16;
    }

    #pragma unroll
    for (int i = 0; i < 4; i++)
        #pragma unroll
        for (int j = 0; j < 4; j++)
            #pragma unroll
            for (int q = 0; q < 4; q++) acc[i][j][q] = 0.f;

    const uint32_t a_base = (uint32_t)(m_w + (lane & 15)) * ROWB + (lane >> 4) * 16;
    const int bg = lane >> 3;
    const uint32_t b_rowoff = (uint32_t)(n_w + ((bg >> 1) * 8) + (lane & 7)) * ROWB;
    const uint32_t b_col = (uint32_t)(bg & 1) * 16;

    auto issue = [&](int c, int s) {
        const __half* sa = X + (size_t)m0 * E_ + c * BKC;
        const __half* sw = W + (size_t)n0 * E_ + c * BKC;
        const uint32_t ab = sbase + (uint32_t)s * STAGE_B;
        const uint32_t bb = ab + TILE_B;
        #pragma unroll
        for (int i = 0; i < 2; i++) {
            CP_ASYNC16(ab + l_soff[i], sa + (size_t)l_row[i] * E_ + l_col[i]);
            CP_ASYNC16(bb + l_soff[i], sw + (size_t)l_row[i] * E_ + l_col[i]);
        }
    };

    auto load_frags = [&](uint32_t stage_base, int ks, uint32_t af[4][4], uint32_t bf[4][2]) {
        const uint32_t at = stage_base;
        const uint32_t bt = stage_base + TILE_B;
        #pragma unroll
        for (int mf = 0; mf < 4; mf++)
            ldsm_x4(af[mf][0], af[mf][1], af[mf][2], af[mf][3],
                    at + a_base + (uint32_t)mf * 16 * ROWB + ks * 32);
        #pragma unroll
        for (int nf2 = 0; nf2 < 2; nf2++) {
            uint32_t r0, r1, r2, r3;
            ldsm_x4(r0, r1, r2, r3,
                    bt + b_rowoff + (uint32_t)nf2 * 16 * ROWB + b_col + ks * 32);
            bf[nf2 * 2 + 0][0] = r0; bf[nf2 * 2 + 0][1] = r1;
            bf[nf2 * 2 + 1][0] = r2; bf[nf2 * 2 + 1][1] = r3;
        }
    };

    auto mma_all = [&](uint32_t af[4][4], uint32_t bf[4][2]) {
        #pragma unroll
        for (int mf = 0; mf < 4; mf++)
            #pragma unroll
            for (int nf = 0; nf < 4; nf++)
                mma_f16(acc[mf][nf], af[mf], bf[nf]);
    };

    issue(0, 0); CP_COMMIT();
    issue(1, 1); CP_COMMIT();
    issue(2, 2); CP_COMMIT();
    CP_WAIT2();
    __syncthreads();
    uint32_t afA[4][4], bfA[4][2];
    uint32_t afB[4][4], bfB[4][2];
    load_frags(sbase, 0, afA, bfA);

    int s_cur = 0;
    for (int it = 0; it < N_CHUNKS; ++it) {
        const uint32_t st_cur = sbase + (uint32_t)s_cur * STAGE_B;

        load_frags(st_cur, 1, afB, bfB);
        mma_all(afA, bfA);

        CP_WAIT1();
        __syncthreads();
        if (it + 3 < N_CHUNKS) issue(it + 3, s_cur);
        CP_COMMIT();

        const int s_nxt = (s_cur + 1 >= 3) ? 0 : s_cur + 1;
        load_frags(sbase + (uint32_t)s_nxt * STAGE_B, 0, afA, bfA);
        mma_all(afB, bfB);

        s_cur = s_nxt;
    }
}

// ---------------- merged QKV projection with fused xpos / transpose epilogues ----------------
__global__ __launch_bounds__(256, 2) void gemm_qkv(
    const float* __restrict__ bq, const float* __restrict__ bk, const float* __restrict__ bv)
{
    extern __shared__ char smem[];
    const uint32_t sbase = smem_u32(smem);
    const int z = blockIdx.z;
    const int m0 = blockIdx.y * 128;
    const int n0 = blockIdx.x * 128;
    const float* bias = (z == 0) ? bq : (z == 1) ? bk : bv;

    float acc[4][4][4];
    gemm_mainloop(sbase, g_X3 + (size_t)z * M_ * E_, g_W3 + (size_t)z * E_ * E_,
                  m0, n0, acc);

    const int tid  = threadIdx.x;
    const int wid  = tid >> 5;
    const int lane = tid & 31;
    const int m_w = (wid & 1) * 64;
    const int n_w = (wid >> 1) * 32;

    if (z < 2) {
        __half* O = (z == 0) ? g_Qh : g_Kh;
        const float alpha = (z == 0) ? 0.125f : 1.f;
        const float sgn = (z == 0) ? 1.f : -1.f;

        float lsj[4], ivf[4];
        #pragma unroll
        for (int nf = 0; nf < 4; nf++) {
            int n = n0 + n_w + nf * 8 + (lane & 3) * 2;
            int j = (n & 63) >> 1;
            float sj = (2.f * j + 25.6f) / 89.6f;
            lsj[nf] = log2f(sj) * (sgn / 1024.f);
            ivf[nf] = exp2f(-(float)j * (13.287712379549449f / 32.f));
        }

        #pragma unroll
        for (int mf = 0; mf < 4; mf++) {
            #pragma unroll
            for (int half = 0; half < 2; half++) {
                const int m = m0 + m_w + mf * 16 + (lane >> 2) + half * 8;
                const int bb = m >> 10;
                const int t  = m & 1023;
                const float pos = (float)(t - 512);
                #pragma unroll
                for (int nf = 0; nf < 4; nf++) {
                    const int n = n0 + n_w + nf * 8 + (lane & 3) * 2;
                    const int h = n >> 6, d = n & 63;
                    float y1 = (acc[mf][nf][half * 2 + 0] + __ldg(bias + n)) * alpha;
                    float y2 = (acc[mf][nf][half * 2 + 1] + __ldg(bias + n + 1)) * alpha;
                    float sc = exp2f(lsj[nf] * pos);
                    float sn, cs;
                    sincosf((float)t * ivf[nf], &sn, &cs);
                    cs *= sc; sn *= sc;
                    float o1 = y1 * cs - y2 * sn;
                    float o2 = y2 * cs + y1 * sn;
                    size_t ob = (((size_t)(bb * H_ + h)) * T_ + t) * D_ + d;
                    *reinterpret_cast<uint32_t*>(O + ob) = pack_h2(o1, o2);
                }
            }
        }
    } else {
        float* tr = reinterpret_cast<float*>(smem);   // [64][132] fp32 = 33792 B
        __syncthreads();
        #pragma unroll
        for (int half_n = 0; half_n < 2; half_n++) {
            if (((wid >> 1) >> 1) == half_n) {
                #pragma unroll
                for (int mf = 0; mf < 4; mf++)
                    #pragma unroll
                    for (int half = 0; half < 2; half++) {
                        const int m_local = m_w + mf * 16 + (lane >> 2) + half * 8;
                        #pragma unroll
                        for (int nf = 0; nf < 4; nf++) {
                            const int dd = ((wid >> 1) & 1) * 32 + nf * 8 + (lane & 3) * 2;
                            const int n = n0 + half_n * 64 + dd;
                            tr[dd * 132 + m_local] =
                                acc[mf][nf][half * 2 + 0] + __ldg(bias + n);
                            tr[(dd + 1) * 132 + m_local] =
                                acc[mf][nf][half * 2 + 1] + __ldg(bias + n + 1);
                        }
                    }
            }
            __syncthreads();
            {
                const int d = tid >> 2;
                const int tpart = (tid & 3) * 32;
                const int h = (n0 >> 6) + half_n;
                const int bh = (m0 >> 10) * H_ + h;
                const size_t ob = ((size_t)bh * D_ + d) * T_ + (m0 & 1023) + tpart;
                const float* row = tr + d * 132 + tpart;
                #pragma unroll
                for (int k = 0; k < 32; k += 2) {
                    *reinterpret_cast<uint32_t*>(g_Vt + ob + k) =
                        pack_h2(row[k], row[k + 1]);
                }
            }
            __syncthreads();
        }
    }
}

// ---------------- output projection ----------------
__global__ __launch_bounds__(256, 2) void gemm_out(
    const float* __restrict__ bias, float* __restrict__ out)
{
    extern __shared__ char smem[];
    const uint32_t sbase = smem_u32(smem);
    const int m0 = blockIdx.y * 128;
    const int n0 = blockIdx.x * 128;

    float acc[4][4][4];
    gemm_mainloop(sbase, g_X3, g_Wo, m0, n0, acc);

    const int tid  = threadIdx.x;
    const int wid  = tid >> 5;
    const int lane = tid & 31;
    const int m_w = (wid & 1) * 64;
    const int n_w = (wid >> 1) * 32;

    #pragma unroll
    for (int mf = 0; mf < 4; mf++) {
        #pragma unroll
        for (int half = 0; half < 2; half++) {
            const int m = m0 + m_w + mf * 16 + (lane >> 2) + half * 8;
            #pragma unroll
            for (int nf = 0; nf < 4; nf++) {
                const int n = n0 + n_w + nf * 8 + (lane & 3) * 2;
                float2 v;
                v.x = acc[mf][nf][half * 2 + 0] + __ldg(bias + n);
                v.y = acc[mf][nf][half * 2 + 1] + __ldg(bias + n + 1);
                *reinterpret_cast<float2*>(out + (size_t)m * E_ + n) = v;
            }
        }
    }
}

// ================= Flash attention, fp16, fixed-shift softmax (R14 proven) =================
#define ASM_ST0  8192
#define ASM_STS  16384
#define ATTN_SMEM 40960

__global__ __launch_bounds__(128) void attn_mma()
{
    extern __shared__ char smem[];
    const uint32_t sb = smem_u32(smem);
    const int tid  = threadIdx.x;
    const int wid  = tid >> 5;
    const int lane = tid & 31;
    const int bh = blockIdx.x;
    const int qt = blockIdx.y;

    auto issue_kv = [&](int st, int s) {
        const int s0 = st * 64;
        const uint32_t base = sb + ASM_ST0 + (uint32_t)s * ASM_STS;
        const __half* kh = g_Kh + ((size_t)bh * T_ + s0) * D_;
        const __half* vh = g_Vt + (size_t)bh * D_ * T_ + s0;
        #pragma unroll
        for (int i = 0; i < 4; i++) {
            int idx = tid + i * 128;
            int row = idx >> 3, seg = idx & 7;
            uint32_t off = (uint32_t)row * 128 + ((seg ^ (row & 7)) * 16);
            CP_ASYNC16(base + off,        kh + (size_t)row * D_ + seg * 8);
            CP_ASYNC16(base + 8192 + off, vh + (size_t)row * T_ + seg * 8);
        }
    };

    {
        const __half* qh = g_Qh + ((size_t)bh * T_ + qt * 64) * D_;
        #pragma unroll
        for (int i = 0; i < 4; i++) {
            int idx = tid + i * 128;
            int row = idx >> 3, seg = idx & 7;
            uint32_t off = (uint32_t)row * 128 + ((seg ^ (row & 7)) * 16);
            CP_ASYNC16(sb + off, qh + (size_t)row * D_ + seg * 8);
        }
        issue_kv(0, 0);
        CP_COMMIT(); CP_WAIT0();
        __syncthreads();
    }

    uint32_t qf[4][4];
    {
        const int row = wid * 16 + (lane & 15);
        const uint32_t rb = (uint32_t)row * 128;
        #pragma unroll
        for (int ks = 0; ks < 4; ks++) {
            int seg = ks * 2 + (lane >> 4);
            uint32_t off = rb + ((seg ^ (row & 7)) * 16);
            ldsm_x4(qf[ks][0], qf[ks][1], qf[ks][2], qf[ks][3], sb + off);
        }
    }

    float l0 = 0.f, l1 = 0.f;
    float o[8][4];
    #pragma unroll
    for (int nf = 0; nf < 8; nf++)
        #pragma unroll
        for (int q = 0; q < 4; q++) o[nf][q] = 0.f;

    const int bg = lane >> 3;
    const int brow_lo = ((bg >> 1) * 8) + (lane & 7);
    const int bseg0 = bg & 1;

    for (int st = 0; st < 16; st++) {
        const int buf = st & 1;
        if (st + 1 < 16) issue_kv(st + 1, buf ^ 1);
        CP_COMMIT();

        const uint32_t kbase = sb + ASM_ST0 + (uint32_t)buf * ASM_STS;
        const uint32_t vbase = kbase + 8192;

        float sacc[8][4];
        #pragma unroll
        for (int nf = 0; nf < 8; nf++)
            #pragma unroll
            for (int q = 0; q < 4; q++) sacc[nf][q] = 0.f;

        #pragma unroll
        for (int ks = 0; ks < 4; ks++) {
            uint32_t bf[8][2];
            #pragma unroll
            for (int nf2 = 0; nf2 < 4; nf2++) {
                int row = nf2 * 16 + brow_lo;
                int seg = (ks * 2 + bseg0) ^ (row & 7);
                uint32_t r0, r1, r2, r3;
                ldsm_x4(r0, r1, r2, r3, kbase + (uint32_t)row * 128 + seg * 16);
                bf[nf2 * 2 + 0][0] = r0; bf[nf2 * 2 + 0][1] = r1;
                bf[nf2 * 2 + 1][0] = r2; bf[nf2 * 2 + 1][1] = r3;
            }
            #pragma unroll
            for (int nf = 0; nf < 8; nf++)
                mma_f16(sacc[nf], qf[ks], bf[nf]);
        }

        #pragma unroll
        for (int nf = 0; nf < 8; nf++) {
            float e0 = __expf(sacc[nf][0]);
            float e1 = __expf(sacc[nf][1]);
            float e2 = __expf(sacc[nf][2]);
            float e3 = __expf(sacc[nf][3]);
            l0 += e0 + e1; l1 += e2 + e3;
            sacc[nf][0] = e0; sacc[nf][1] = e1;
            sacc[nf][2] = e2; sacc[nf][3] = e3;
        }

        uint32_t pf[4][4];
        #pragma unroll
        for (int ks = 0; ks < 4; ks++) {
            pf[ks][0] = pack_h2(sacc[2 * ks][0],     sacc[2 * ks][1]);
            pf[ks][1] = pack_h2(sacc[2 * ks][2],     sacc[2 * ks][3]);
            pf[ks][2] = pack_h2(sacc[2 * ks + 1][0], sacc[2 * ks + 1][1]);
            pf[ks][3] = pack_h2(sacc[2 * ks + 1][2], sacc[2 * ks + 1][3]);
        }

        #pragma unroll
        for (int ks = 0; ks < 4; ks++) {
            uint32_t bf[8][2];
            #pragma unroll
            for (int nf2 = 0; nf2 < 4; nf2++) {
                int row = nf2 * 16 + brow_lo;
                int seg = (ks * 2 + bseg0) ^ (row & 7);
                uint32_t r0, r1, r2, r3;
                ldsm_x4(r0, r1, r2, r3, vbase + (uint32_t)row * 128 + seg * 16);
                bf[nf2 * 2 + 0][0] = r0; bf[nf2 * 2 + 0][1] = r1;
                bf[nf2 * 2 + 1][0] = r2; bf[nf2 * 2 + 1][1] = r3;
            }
            #pragma unroll
            for (int nf = 0; nf < 8; nf++)
                mma_f16(o[nf], pf[ks], bf[nf]);
        }

        CP_WAIT0();
        __syncthreads();
    }

    l0 += __shfl_xor_sync(0xffffffffu, l0, 1);
    l0 += __shfl_xor_sync(0xffffffffu, l0, 2);
    l1 += __shfl_xor_sync(0xffffffffu, l1, 1);
    l1 += __shfl_xor_sync(0xffffffffu, l1, 2);
    const float inv0 = 1.f / l0;
    const float inv1 = 1.f / l1;

    const int t0 = qt * 64 + wid * 16 + (lane >> 2);
    const int b = bh >> 4, h = bh & 15;
    const size_t c0i = ((size_t)(b * T_ + t0)) * E_ + h * D_ + (lane & 3) * 2;
    const size_t c1i = c0i + (size_t)8 * E_;
    #pragma unroll
    for (int nf = 0; nf < 8; nf++) {
        *reinterpret_cast<uint32_t*>(g_X3 + c0i + nf * 8) =
            pack_h2(o[nf][0] * inv0, o[nf][1] * inv0);
        *reinterpret_cast<uint32_t*>(g_X3 + c1i + nf * 8) =
            pack_h2(o[nf][2] * inv1, o[nf][3] * inv1);
    }
}

// ---------------- launch ----------------
extern "C" void kernel_launch(void* const* d_in, const int* in_sizes, int n_in,
                              void* d_out, int out_size)
{
    const float* query = (const float*)d_in[0];
    const float* key   = (const float*)d_in[1];
    const float* value = (const float*)d_in[2];
    const float* wq    = (const float*)d_in[3];
    const float* bq    = (const float*)d_in[4];
    const float* wk    = (const float*)d_in[5];
    const float* bk    = (const float*)d_in[6];
    const float* wv    = (const float*)d_in[7];
    const float* bv    = (const float*)d_in[8];
    const float* wo    = (const float*)d_in[9];
    const float* bo    = (const float*)d_in[10];
    float* out = (float*)d_out;

    static bool attr_done = false;
    if (!attr_done) {
        cudaFuncSetAttribute(gemm_qkv, cudaFuncAttributeMaxDynamicSharedMemorySize, GEMM_SMEM);
        cudaFuncSetAttribute(gemm_out, cudaFuncAttributeMaxDynamicSharedMemorySize, GEMM_SMEM);
        cudaFuncSetAttribute(attn_mma, cudaFuncAttributeMaxDynamicSharedMemorySize, ATTN_SMEM);
        attr_done = true;
    }

    const int actn16 = (M_ * E_) / 16;   // 524,288

    conv_all<<<dim3(actn16 / 256, 1, 7), 256>>>(query, key, value, wq, wk, wv, wo);

    gemm_qkv<<<dim3(E_ / 128, M_ / 128, 3), 256, GEMM_SMEM>>>(bq, bk, bv);

    attn_mma<<<dim3(BH_, T_ / 64), 128, ATTN_SMEM>>>();   // writes C fp16 into X3 slot 0

    gemm_out<<<dim3(E_ / 128, M_ / 128), 256, GEMM_SMEM>>>(bo, out);
}